// round 13
// baseline (speedup 1.0000x reference)
#include <cuda_runtime.h>

// out[i] = (-2*pi^2 + a^2) * sin(pi*x0) * sin(pi*x1)   (P = 1)
//
// R7-proven L2 plan: output (67 MB) stored with evict_last -> dirty lines
// overwritten in L2 every graph replay, steady-state DRAM writes ~0
// (measured 201 -> 143 MB/iter). Input pinning tested at 40 MB (R8, leaked)
// and 24 MB (R9, neutral): the evict_last pool is consumed by the output;
// input streams with evict_first.
//
// New in this round: persistent grid-stride kernel, 1184 CTAs = 148 SMs x 8.
// Collapses ~14 one-shot waves into 1 (no wave-transition cost, tail spread
// paid once), and the x2-unrolled loop lets ptxas pipeline next-iter loads
// under current-iter MUFU work.

#define PI_F 3.14159265358979323846f

__device__ __forceinline__ float4 ld_stream(const float4* p, unsigned long long pol)
{
    float4 v;
    asm volatile("ld.global.nc.L2::cache_hint.v4.f32 {%0,%1,%2,%3}, [%4], %5;"
                 : "=f"(v.x), "=f"(v.y), "=f"(v.z), "=f"(v.w)
                 : "l"(p), "l"(pol));
    return v;
}

__device__ __forceinline__ void st_pin(float4* p, float4 v, unsigned long long pol)
{
    asm volatile("st.global.L2::cache_hint.v4.f32 [%0], {%1,%2,%3,%4}, %5;"
                 :: "l"(p), "f"(v.x), "f"(v.y), "f"(v.z), "f"(v.w), "l"(pol)
                 : "memory");
}

__device__ __forceinline__ float4 compute4(float4 p0, float4 p1, float coef)
{
    float4 r;
    r.x = coef * __sinf(PI_F * p0.x) * __sinf(PI_F * p0.y);
    r.y = coef * __sinf(PI_F * p0.z) * __sinf(PI_F * p0.w);
    r.z = coef * __sinf(PI_F * p1.x) * __sinf(PI_F * p1.y);
    r.w = coef * __sinf(PI_F * p1.z) * __sinf(PI_F * p1.w);
    return r;
}

#define NBLOCKS  1184   // 148 SMs x 8 CTAs
#define NTHREADS 256

__global__ void __launch_bounds__(NTHREADS)
helm_kernel(const float4* __restrict__ in,   // N/2 float4 (x0,x1 pairs)
            const float* __restrict__ a,
            float4* __restrict__ out,        // N/4 float4 outputs
            int n4)                           // N/4 output float4s
{
    unsigned long long pol_first, pol_last;
    asm("createpolicy.fractional.L2::evict_first.b64 %0, 1.0;" : "=l"(pol_first));
    asm("createpolicy.fractional.L2::evict_last.b64 %0, 1.0;"  : "=l"(pol_last));

    float av = __ldg(a);
    float coef = fmaf(av, av, -2.0f * PI_F * PI_F);

    const int stride = NBLOCKS * NTHREADS;          // 303104
    int i = blockIdx.x * NTHREADS + threadIdx.x;

    // n4 = 4194304 = 13 * stride + 253952; handle bulk with x2 unroll,
    // remainder with a guarded tail iteration.
    int bulk_end = n4 - 2 * stride;                 // safe double-step bound
    for (; i < bulk_end; i += 2 * stride) {
        int j = i + stride;
        const float4* pa = in + 2 * (size_t)i;
        const float4* pb = in + 2 * (size_t)j;
        float4 a0 = ld_stream(pa + 0, pol_first);
        float4 a1 = ld_stream(pa + 1, pol_first);
        float4 b0 = ld_stream(pb + 0, pol_first);
        float4 b1 = ld_stream(pb + 1, pol_first);
        st_pin(out + i, compute4(a0, a1, coef), pol_last);
        st_pin(out + j, compute4(b0, b1, coef), pol_last);
    }
    for (; i < n4; i += stride) {
        const float4* p = in + 2 * (size_t)i;
        float4 p0 = ld_stream(p + 0, pol_first);
        float4 p1 = ld_stream(p + 1, pol_first);
        st_pin(out + i, compute4(p0, p1, coef), pol_last);
    }
}

extern "C" void kernel_launch(void* const* d_in, const int* in_sizes, int n_in,
                              void* d_out, int out_size)
{
    const float* input = (const float*)d_in[0];   // [N, 2] flattened
    const float* a     = (const float*)d_in[1];   // [1]
    float* out         = (float*)d_out;           // [N, 1]

    int n  = in_sizes[0] / 2;   // 16777216 rows
    int n4 = n / 4;             // 4194304

    helm_kernel<<<NBLOCKS, NTHREADS>>>(
        (const float4*)input, a, (float4*)out, n4);
}

// round 14
// speedup vs baseline: 1.1482x; 1.1482x over previous
#include <cuda_runtime.h>

// out[i] = (-2*pi^2 + a^2) * sin(pi*x0) * sin(pi*x1)   (P = 1)
//
// R7-proven L2 plan (kept): output (67 MB) stored evict_last -> overwritten
// in L2 every graph replay, steady-state DRAM writes ~0 (201->143 MB/iter
// measured). Input streams evict_first (pinning it was tested R8/R9: the
// evict_last pool is consumed by the output alone).
//
// New: 2 outputs per thread at i and i+256 (block covers 512 consecutive
// output float4s). All 4 input LDG.128 are independent and front-batched
// (MLP_p1 = 4) while lane addressing stays dense: the two companion loads of
// each output pair fully consume the 8 touched 128B lines (no dead sectors;
// R5's mistake was 4 *consecutive* float4s per thread -> 64B lane stride).
// One-shot grid (8192 CTAs) — R13 showed the persistent shape regresses.

#define PI_F 3.14159265358979323846f

__device__ __forceinline__ float4 ld_stream(const float4* p, unsigned long long pol)
{
    float4 v;
    asm volatile("ld.global.nc.L2::cache_hint.v4.f32 {%0,%1,%2,%3}, [%4], %5;"
                 : "=f"(v.x), "=f"(v.y), "=f"(v.z), "=f"(v.w)
                 : "l"(p), "l"(pol));
    return v;
}

__device__ __forceinline__ void st_pin(float4* p, float4 v, unsigned long long pol)
{
    asm volatile("st.global.L2::cache_hint.v4.f32 [%0], {%1,%2,%3,%4}, %5;"
                 :: "l"(p), "f"(v.x), "f"(v.y), "f"(v.z), "f"(v.w), "l"(pol)
                 : "memory");
}

__device__ __forceinline__ float4 compute4(float4 p0, float4 p1, float coef)
{
    float4 r;
    r.x = coef * __sinf(PI_F * p0.x) * __sinf(PI_F * p0.y);
    r.y = coef * __sinf(PI_F * p0.z) * __sinf(PI_F * p0.w);
    r.z = coef * __sinf(PI_F * p1.x) * __sinf(PI_F * p1.y);
    r.w = coef * __sinf(PI_F * p1.z) * __sinf(PI_F * p1.w);
    return r;
}

#define NTHREADS 256

__global__ void __launch_bounds__(NTHREADS)
helm_kernel(const float4* __restrict__ in,   // N/2 float4 (x0,x1 pairs)
            const float* __restrict__ a,
            float4* __restrict__ out,        // N/4 float4 outputs
            int n4)                           // N/4 output float4s
{
    // Block owns 512 consecutive output float4s; thread handles 2 of them.
    int i0 = blockIdx.x * (2 * NTHREADS) + threadIdx.x;   // first output
    int i1 = i0 + NTHREADS;                               // second output
    if (i1 >= n4) {           // n4 % 512 == 0 for this shape; guard anyway
        if (i0 >= n4) return;
        i1 = i0;              // degenerate: duplicate work, still correct
    }

    unsigned long long pol_first, pol_last;
    asm("createpolicy.fractional.L2::evict_first.b64 %0, 1.0;" : "=l"(pol_first));
    asm("createpolicy.fractional.L2::evict_last.b64 %0, 1.0;"  : "=l"(pol_last));

    float av = __ldg(a);
    float coef = fmaf(av, av, -2.0f * PI_F * PI_F);

    // 4 independent, front-batched LDG.128 (MLP_p1 = 4), dense coalescing
    const float4* pa = in + 2 * (size_t)i0;
    const float4* pb = in + 2 * (size_t)i1;
    float4 a0 = ld_stream(pa + 0, pol_first);
    float4 a1 = ld_stream(pa + 1, pol_first);
    float4 b0 = ld_stream(pb + 0, pol_first);
    float4 b1 = ld_stream(pb + 1, pol_first);

    st_pin(out + i0, compute4(a0, a1, coef), pol_last);
    st_pin(out + i1, compute4(b0, b1, coef), pol_last);
}

extern "C" void kernel_launch(void* const* d_in, const int* in_sizes, int n_in,
                              void* d_out, int out_size)
{
    const float* input = (const float*)d_in[0];   // [N, 2] flattened
    const float* a     = (const float*)d_in[1];   // [1]
    float* out         = (float*)d_out;           // [N, 1]

    int n  = in_sizes[0] / 2;   // 16777216 rows
    int n4 = n / 4;             // 4194304 output float4s

    int blocks = (n4 + 2 * NTHREADS - 1) / (2 * NTHREADS);   // 8192

    helm_kernel<<<blocks, NTHREADS>>>(
        (const float4*)input, a, (float4*)out, n4);
}